// round 14
// baseline (speedup 1.0000x reference)
#include <cuda_runtime.h>
#include <cuda_bf16.h>
#include <math.h>
#include <stdint.h>

// Problem constants (fixed by setup_inputs)
#define ND 12288   // D
#define NH 1024    // HASH
#define NU 32      // units
#define NK 128     // BASIS
#define NB 16      // batch
#define NDEPTH 16

#define KS_BIG 96    // split-K for the D x D transform GEMM (grid 12x96=1152, ~4 waves)
#define KL_BIG 128   // k-rows per big block
#define KS_HASH 192  // split-K for the hash GEMM (grid 2x192=384)
#define KL_HASH 64   // k-rows per hash block
#define FC 8         // f-chunks for coeff

// ---------------- device scratch (no allocations allowed) ----------------
__device__ float g_xf[2 * NB * ND];                 // ping-pong xf
__device__ float g_part[KS_BIG * NB * ND];          // big-GEMM split-K partials (75.5MB)
__device__ float g_hpart[KS_HASH * NB * NH];        // hash split-K partials
__device__ float g_h[NB * NH];                      // current hash
__device__ float g_gram[NU * NK * NK];              // per-unit Gram B^T B
__device__ float g_coeffp[FC * NU * NB * NK];       // coeff partials [fc][u][b][k]
__device__ float g_coeff[NB * NU * NK];             // summed coeff [b][u][k]
__device__ unsigned long long g_amax[NB];           // encoded masked argmax
__device__ int   g_routeh[NB * NDEPTH];             // route history (masking)

// ---------------- f32x2 helpers ----------------
__device__ __forceinline__ unsigned long long pk2(float lo, float hi) {
    unsigned long long r;
    asm("mov.b64 %0, {%1, %2};" : "=l"(r) : "f"(lo), "f"(hi));
    return r;
}
__device__ __forceinline__ void upk2(unsigned long long v, float& lo, float& hi) {
    asm("mov.b64 {%0, %1}, %2;" : "=f"(lo), "=f"(hi) : "l"(v));
}
__device__ __forceinline__ unsigned long long f2fma(unsigned long long a,
                                                    unsigned long long b,
                                                    unsigned long long c) {
    unsigned long long d;
    asm("fma.rn.f32x2 %0, %1, %2, %3;" : "=l"(d) : "l"(a), "l"(b), "l"(c));
    return d;
}

// ---------------- zero the hash-accumulator region of d_out ----------------
__global__ void k_init(float* __restrict__ out) {
    int i = blockIdx.x * 256 + threadIdx.x;
    if (i < NB * NH) out[i] = 0.0f;
}

// ---------------- Gram: G[u] = basis[u]^T basis[u] (128x128 per unit) ----------------
__global__ void __launch_bounds__(128) k_gram(const float* __restrict__ basis) {
    int u = blockIdx.x;
    int ic = blockIdx.y;
    int tid = threadIdx.x;
    __shared__ float rows[8][128];
    unsigned long long acc[16];
    #pragma unroll
    for (int p = 0; p < 16; p++) acc[p] = 0ull;

    for (int fb = 0; fb < 128; fb++) {
        __syncthreads();
        #pragma unroll
        for (int rr = 0; rr < 8; rr++)
            rows[rr][tid] = __ldg(basis + ((size_t)u * NH + fb * 8 + rr) * NK + tid);
        __syncthreads();
        #pragma unroll
        for (int rr = 0; rr < 8; rr++) {
            float bj = rows[rr][tid];
            unsigned long long wp = pk2(bj, bj);
            const ulonglong2* ip = (const ulonglong2*)&rows[rr][ic * 32];
            #pragma unroll
            for (int q = 0; q < 8; q++) {
                ulonglong2 v = ip[q];
                acc[2 * q + 0] = f2fma(v.x, wp, acc[2 * q + 0]);
                acc[2 * q + 1] = f2fma(v.y, wp, acc[2 * q + 1]);
            }
        }
    }
    #pragma unroll
    for (int p = 0; p < 16; p++) {
        float lo, hi;
        upk2(acc[p], lo, hi);
        g_gram[((size_t)u * NK + ic * 32 + 2 * p + 0) * NK + tid] = lo;
        g_gram[((size_t)u * NK + ic * 32 + 2 * p + 1) * NK + tid] = hi;
    }
}

// ---------------- FMA core for one k-row: acc[c][p] += xs_pair[p] * w[c] ----------------
__device__ __forceinline__ void fma_row(const float* xsk, float4 w,
                                        unsigned long long* acc) {
    unsigned long long wx = pk2(w.x, w.x);
    unsigned long long wy = pk2(w.y, w.y);
    unsigned long long wz = pk2(w.z, w.z);
    unsigned long long ww = pk2(w.w, w.w);
    const ulonglong2* xr = (const ulonglong2*)xsk;
    ulonglong2 q0 = xr[0], q1 = xr[1], q2 = xr[2], q3 = xr[3];
    unsigned long long xp[8] = {q0.x, q0.y, q1.x, q1.y, q2.x, q2.y, q3.x, q3.y};
    #pragma unroll
    for (int p = 0; p < 8; p++) {
        acc[0 * 8 + p] = f2fma(xp[p], wx, acc[0 * 8 + p]);
        acc[1 * 8 + p] = f2fma(xp[p], wy, acc[1 * 8 + p]);
        acc[2 * 8 + p] = f2fma(xp[p], wz, acc[2 * 8 + p]);
        acc[3 * 8 + p] = f2fma(xp[p], ww, acc[3 * 8 + p]);
    }
}

// ---------------- split-K GEMM partial, 4 cols/thread, reg prefetch depth 4 ----------
// out[ks][b][col] = sum_{k in chunk} X[b][k] * W[k][col]
template <bool STREAM, int TPB, int KLEN, int MAXB>
__global__ void __launch_bounds__(TPB, MAXB)
k_gemm4(const float* __restrict__ X, const float* __restrict__ W,
        int N, float* __restrict__ out) {
    __shared__ float xs[KLEN][16];
    int tid = threadIdx.x;
    int col = (blockIdx.x * TPB + tid) * 4;
    int k0 = blockIdx.y * KLEN;

    // stage X[:, k0..k0+KLEN) transposed into xs[k][b]
    #pragma unroll 4
    for (int idx = tid; idx < KLEN * 4; idx += TPB) {   // float4 units
        int b = idx & 15;
        int kq = idx >> 4;
        float4 v = *(const float4*)(X + (size_t)b * ND + k0 + kq * 4);
        xs[kq * 4 + 0][b] = v.x;
        xs[kq * 4 + 1][b] = v.y;
        xs[kq * 4 + 2][b] = v.z;
        xs[kq * 4 + 3][b] = v.w;
    }

    unsigned long long acc[32];        // [c(4)][p(8)]: batch pairs (2p,2p+1)
    #pragma unroll
    for (int i = 0; i < 32; i++) acc[i] = 0ull;

    const float* Wp = W + (size_t)k0 * N + col;
    const float* Wpf = Wp + (size_t)4 * N;
    float4 wbuf[4];
    #pragma unroll
    for (int i = 0; i < 4; i++)
        wbuf[i] = STREAM ? __ldcs((const float4*)(Wp + (size_t)i * N))
                         : __ldg((const float4*)(Wp + (size_t)i * N));

    __syncthreads();

    #pragma unroll 4
    for (int k = 0; k < KLEN - 4; k++) {
        float4 w = wbuf[k & 3];
        wbuf[k & 3] = STREAM ? __ldcs((const float4*)Wpf)
                             : __ldg((const float4*)Wpf);
        Wpf += N;
        fma_row(&xs[k][0], w, acc);
    }
    #pragma unroll
    for (int k = KLEN - 4; k < KLEN; k++)
        fma_row(&xs[k][0], wbuf[k & 3], acc);

    float* op = out + (size_t)blockIdx.y * (NB * (size_t)N) + col;
    #pragma unroll
    for (int p = 0; p < 8; p++) {
        float4 r0, r1;
        upk2(acc[0 * 8 + p], r0.x, r1.x);
        upk2(acc[1 * 8 + p], r0.y, r1.y);
        upk2(acc[2 * 8 + p], r0.z, r1.z);
        upk2(acc[3 * 8 + p], r0.w, r1.w);
        *(float4*)(op + (size_t)(2 * p + 0) * N) = r0;
        *(float4*)(op + (size_t)(2 * p + 1) * N) = r1;
    }
}

// ---------------- reduce KS_BIG partials + bias[route from amax] + tanh -> xf_next ---
__global__ void __launch_bounds__(256) k_reduce_tanh(const float* __restrict__ bias,
                                                     float* __restrict__ Xout) {
    int idx = blockIdx.x * 256 + threadIdx.x;      // float4 index, 49152 total
    int b = idx / 3072;
    int j = (idx - b * 3072) * 4;
    size_t o = (size_t)b * ND + j;
    float4 s = make_float4(0.f, 0.f, 0.f, 0.f);
    #pragma unroll 8
    for (int t = 0; t < KS_BIG; t++) {
        float4 v = *(const float4*)(g_part + (size_t)t * (NB * ND) + o);
        s.x += v.x; s.y += v.y; s.z += v.z; s.w += v.w;
    }
    int r = 31 - (int)(g_amax[b] & 0xffull);       // decode route directly
    float4 bv = *(const float4*)(bias + (size_t)r * ND + j);
    float4 res;
    res.x = tanhf(s.x + bv.x);
    res.y = tanhf(s.y + bv.y);
    res.z = tanhf(s.z + bv.z);
    res.w = tanhf(s.w + bv.w);
    *(float4*)(Xout + o) = res;
}

// ---------------- reduce KS_HASH hash partials -> g_h; also reset g_amax ------------
__global__ void __launch_bounds__(256) k_hreduce() {
    int tid = threadIdx.x;
    if (blockIdx.x == 0 && tid < NB) g_amax[tid] = 0ull;
    int o = tid & 31;                      // output within block (float4)
    int g = tid >> 5;                      // p-group 0..7
    int e4 = blockIdx.x * 32 + o;          // float4 elem 0..4095
    __shared__ float4 red[256];

    float4 s = make_float4(0.f, 0.f, 0.f, 0.f);
    #pragma unroll 8
    for (int p = 0; p < KS_HASH / 8; p++) {
        float4 v = *(const float4*)(g_hpart +
                                    (size_t)(g * (KS_HASH / 8) + p) * (NB * NH) + e4 * 4);
        s.x += v.x; s.y += v.y; s.z += v.z; s.w += v.w;
    }
    red[g * 32 + o] = s;
    __syncthreads();
    #pragma unroll
    for (int gg = 4; gg >= 1; gg >>= 1) {
        if (g < gg) {
            float4 a = red[g * 32 + o];
            float4 c = red[(g + gg) * 32 + o];
            a.x += c.x; a.y += c.y; a.z += c.z; a.w += c.w;
            red[g * 32 + o] = a;
        }
        __syncthreads();
    }
    if (g == 0) *(float4*)(g_h + e4 * 4) = red[o];
}

// ---------------- coeff partial: coeffp[fc][u][b][k] = sum_{f chunk} h[b][f]*basis[u][f][k] ----
__global__ void __launch_bounds__(128) k_coeff(const float* __restrict__ basis) {
    int u = blockIdx.x;
    int fc = blockIdx.y;
    int tid = threadIdx.x;
    __shared__ float hs[128][16];
    #pragma unroll
    for (int it = 0; it < 16; it++) {
        int idx = tid + it * 128;
        int b = idx & 15;
        int f = idx >> 4;
        hs[f][b] = g_h[b * NH + fc * 128 + f];
    }
    __syncthreads();

    unsigned long long acc[8];
    #pragma unroll
    for (int i = 0; i < 8; i++) acc[i] = 0ull;

    const float* bp = basis + ((size_t)u * NH + fc * 128) * NK + tid;
    #pragma unroll 16
    for (int f = 0; f < 128; f++) {
        float bv = __ldg(bp + (size_t)f * NK);
        unsigned long long wp = pk2(bv, bv);
        const ulonglong2* xr = (const ulonglong2*)&hs[f][0];
        ulonglong2 q0 = xr[0], q1 = xr[1], q2 = xr[2], q3 = xr[3];
        acc[0] = f2fma(q0.x, wp, acc[0]);
        acc[1] = f2fma(q0.y, wp, acc[1]);
        acc[2] = f2fma(q1.x, wp, acc[2]);
        acc[3] = f2fma(q1.y, wp, acc[3]);
        acc[4] = f2fma(q2.x, wp, acc[4]);
        acc[5] = f2fma(q2.y, wp, acc[5]);
        acc[6] = f2fma(q3.x, wp, acc[6]);
        acc[7] = f2fma(q3.y, wp, acc[7]);
    }
    #pragma unroll
    for (int p = 0; p < 8; p++) {
        float lo, hi;
        upk2(acc[p], lo, hi);
        g_coeffp[(((size_t)fc * NU + u) * NB + 2 * p + 0) * NK + tid] = lo;
        g_coeffp[(((size_t)fc * NU + u) * NB + 2 * p + 1) * NK + tid] = hi;
    }
}

// ---------------- mags + fused masked argmax: c^T G c -> encoded atomicMax ----------
__global__ void __launch_bounds__(128) k_mags(int step) {
    int b = blockIdx.x;
    int u = blockIdx.y;
    int tid = threadIdx.x;
    __shared__ float cs[128];
    __shared__ float red[128];

    float c = 0.f;
    #pragma unroll
    for (int fc = 0; fc < FC; fc++)
        c += g_coeffp[(((size_t)fc * NU + u) * NB + b) * NK + tid];
    cs[tid] = c;
    g_coeff[((size_t)b * NU + u) * NK + tid] = c;
    __syncthreads();

    float v = 0.f;
    const float* gp = g_gram + (size_t)u * NK * NK + tid;
    #pragma unroll 8
    for (int i = 0; i < 128; i++) v += gp[(size_t)i * NK] * cs[i];
    red[tid] = v * cs[tid];
    __syncthreads();
    for (int off = 64; off > 0; off >>= 1) {
        if (tid < off) red[tid] += red[tid + off];
        __syncthreads();
    }
    if (tid == 0) {
        float m = fmaxf(red[0], 0.0f);
        bool masked = false;
        for (int t = 0; t < step; t++)
            if (g_routeh[b * NDEPTH + t] == u) masked = true;
        if (!masked) {
            unsigned long long e =
                ((unsigned long long)__float_as_uint(m) << 32) |
                (unsigned long long)(31 - u);
            atomicMax(&g_amax[b], e);
        }
    }
}

// ---------------- residual: decode route; out[b][f] += h[b][f] - (basis[u] @ c)[f] ----
__global__ void __launch_bounds__(128) k_resid(const float* __restrict__ basis,
                                               float* __restrict__ out,
                                               int step, float* __restrict__ routes_out) {
    int b = blockIdx.x;
    int fc = blockIdx.y;
    int tid = threadIdx.x;
    int f = fc * 128 + tid;
    __shared__ float cs[128];
    __shared__ int su;
    if (tid == 0) {
        int u = 31 - (int)(g_amax[b] & 0xffull);
        su = u;
        if (fc == 0) {
            g_routeh[b * NDEPTH + step] = u;
            if (routes_out) routes_out[b * NDEPTH + step] = (float)u;
        }
    }
    __syncthreads();
    int u = su;
    cs[tid] = g_coeff[((size_t)b * NU + u) * NK + tid];
    __syncthreads();

    float acc = 0.f;
    const float4* bp = (const float4*)(basis + ((size_t)u * NH + f) * NK);
    #pragma unroll 8
    for (int kq = 0; kq < 32; kq++) {
        float4 v = __ldg(bp + kq);
        acc += v.x * cs[kq * 4 + 0] + v.y * cs[kq * 4 + 1] +
               v.z * cs[kq * 4 + 2] + v.w * cs[kq * 4 + 3];
    }
    int o = b * NH + f;
    out[o] += g_h[o] - acc;
}

// ---------------- launch: two-stream fork/join, multi-wave GEMM ---------------
// main stream (origin): bigGEMM (1152 blocks, ~4 waves) -> reduce_tanh
// s2 (high priority): hash -> hreduce -> coeff -> mags -> (evR) -> resid
extern "C" void kernel_launch(void* const* d_in, const int* in_sizes, int n_in,
                              void* d_out, int out_size) {
    (void)in_sizes; (void)n_in;
    const float* x     = (const float*)d_in[0];
    const float* P     = (const float*)d_in[1];
    const float* basis = (const float*)d_in[2];
    const float* Wt    = (const float*)d_in[3];
    const float* bias  = (const float*)d_in[4];
    float* out = (float*)d_out;
    float* routes_out = (out_size >= NB * NH + NB * NDEPTH) ? out + NB * NH : nullptr;

    float *p_xf = nullptr, *p_part = nullptr, *p_hpart = nullptr;
    cudaGetSymbolAddress((void**)&p_xf, g_xf);
    cudaGetSymbolAddress((void**)&p_part, g_part);
    cudaGetSymbolAddress((void**)&p_hpart, g_hpart);

    // one-time resource setup (no device memory allocation; identical work every call)
    static cudaStream_t s2 = nullptr;
    static cudaEvent_t ev0 = nullptr, evR = nullptr, evX = nullptr, evF = nullptr;
    if (s2 == nullptr) {
        int lo = 0, hi = 0;
        cudaDeviceGetStreamPriorityRange(&lo, &hi);
        cudaStreamCreateWithPriority(&s2, cudaStreamNonBlocking, hi);
        cudaEventCreateWithFlags(&ev0, cudaEventDisableTiming);
        cudaEventCreateWithFlags(&evR, cudaEventDisableTiming);
        cudaEventCreateWithFlags(&evX, cudaEventDisableTiming);
        cudaEventCreateWithFlags(&evF, cudaEventDisableTiming);
    }

    // fork: s2 joins the capture via ev0 recorded on the origin stream
    cudaEventRecord(ev0, 0);
    cudaStreamWaitEvent(s2, ev0, 0);

    // ---- s2 prologue: init out, gram, initial hash + routing step 0 ----
    k_init<<<64, 256, 0, s2>>>(out);
    k_gram<<<dim3(32, 4), 128, 0, s2>>>(basis);
    k_gemm4<false, 128, KL_HASH, 4><<<dim3(2, KS_HASH), 128, 0, s2>>>(x, P, NH, p_hpart);
    k_hreduce<<<128, 256, 0, s2>>>();
    k_coeff<<<dim3(32, FC), 128, 0, s2>>>(basis);
    k_mags<<<dim3(16, 32), 128, 0, s2>>>(0);
    cudaEventRecord(evR, s2);
    k_resid<<<dim3(16, 8), 128, 0, s2>>>(basis, out, 0, routes_out);

    // ---- main prologue: s=0 big GEMM (only needs x) ----
    k_gemm4<true, 256, KL_BIG, 2><<<dim3(12, KS_BIG), 256>>>(x, Wt, ND, p_part);
    cudaStreamWaitEvent(0, evR, 0);
    k_reduce_tanh<<<192, 256>>>(bias, p_xf);              // Xn0 = g_xf[0]
    cudaEventRecord(evX, 0);

    for (int s = 1; s < NDEPTH; s++) {
        const float* Xc = p_xf + (size_t)((s - 1) & 1) * NB * ND;  // Xn_{s-1}

        // s2: hash of Xn_{s-1} + routing step s (interleaves with GEMM waves)
        cudaStreamWaitEvent(s2, evX, 0);
        k_gemm4<false, 128, KL_HASH, 4><<<dim3(2, KS_HASH), 128, 0, s2>>>(Xc, P, NH, p_hpart);
        k_hreduce<<<128, 256, 0, s2>>>();
        k_coeff<<<dim3(32, FC), 128, 0, s2>>>(basis);
        k_mags<<<dim3(16, 32), 128, 0, s2>>>(s);
        cudaEventRecord(evR, s2);
        k_resid<<<dim3(16, 8), 128, 0, s2>>>(basis, out, s, routes_out);

        if (s < NDEPTH - 1) {
            // main: multi-wave big GEMM for this step (reads Xn_{s-1})
            k_gemm4<true, 256, KL_BIG, 2><<<dim3(12, KS_BIG), 256>>>(Xc, Wt, ND, p_part);
            cudaStreamWaitEvent(0, evR, 0);
            float* Xn = p_xf + (size_t)(s & 1) * NB * ND;
            k_reduce_tanh<<<192, 256>>>(bias, Xn);
            cudaEventRecord(evX, 0);
        }
    }
    // final join: all s2 work (incl. last resid writing `out`) back into origin stream
    cudaEventRecord(evF, s2);
    cudaStreamWaitEvent(0, evF, 0);
}

// round 15
// speedup vs baseline: 1.2017x; 1.2017x over previous
#include <cuda_runtime.h>
#include <cuda_bf16.h>
#include <math.h>
#include <stdint.h>

// Problem constants (fixed by setup_inputs)
#define ND 12288   // D
#define NH 1024    // HASH
#define NU 32      // units
#define NK 128     // BASIS
#define NB 16      // batch
#define NDEPTH 16

#define KS_BIG 24    // split-K for the D x D transform GEMM (grid 12x24=288)
#define KL_BIG 512   // k-rows per big block
#define KS_HASH 192  // split-K for the hash GEMM (grid 4x192=768 with 2 cols/thread)
#define KL_HASH 64   // k-rows per hash block
#define FC 8         // f-chunks for coeff

// ---------------- device scratch (no allocations allowed) ----------------
__device__ float g_xf[2 * NB * ND];                 // ping-pong xf
__device__ float g_part[KS_BIG * NB * ND];          // big-GEMM split-K partials
__device__ float g_hpart[KS_HASH * NB * NH];        // hash split-K partials
__device__ float g_h[NB * NH];                      // current hash
__device__ float g_gram[NU * NK * NK];              // per-unit Gram B^T B
__device__ float g_coeffp[FC * NU * NB * NK];       // coeff partials [fc][u][b][k]
__device__ float g_coeff[NB * NU * NK];             // summed coeff [b][u][k]
__device__ unsigned long long g_amax[NB];           // encoded masked argmax
__device__ int   g_routeh[NB * NDEPTH];             // route history (masking)

// ---------------- f32x2 helpers ----------------
__device__ __forceinline__ unsigned long long pk2(float lo, float hi) {
    unsigned long long r;
    asm("mov.b64 %0, {%1, %2};" : "=l"(r) : "f"(lo), "f"(hi));
    return r;
}
__device__ __forceinline__ void upk2(unsigned long long v, float& lo, float& hi) {
    asm("mov.b64 {%0, %1}, %2;" : "=f"(lo), "=f"(hi) : "l"(v));
}
__device__ __forceinline__ unsigned long long f2fma(unsigned long long a,
                                                    unsigned long long b,
                                                    unsigned long long c) {
    unsigned long long d;
    asm("fma.rn.f32x2 %0, %1, %2, %3;" : "=l"(d) : "l"(a), "l"(b), "l"(c));
    return d;
}

// ---------------- zero the hash-accumulator region of d_out ----------------
__global__ void k_init(float* __restrict__ out) {
    int i = blockIdx.x * 256 + threadIdx.x;
    if (i < NB * NH) out[i] = 0.0f;
}

// ---------------- Gram: G[u] = basis[u]^T basis[u] (128x128 per unit) ----------------
__global__ void __launch_bounds__(128) k_gram(const float* __restrict__ basis) {
    int u = blockIdx.x;
    int ic = blockIdx.y;
    int tid = threadIdx.x;
    __shared__ float rows[8][128];
    unsigned long long acc[16];
    #pragma unroll
    for (int p = 0; p < 16; p++) acc[p] = 0ull;

    for (int fb = 0; fb < 128; fb++) {
        __syncthreads();
        #pragma unroll
        for (int rr = 0; rr < 8; rr++)
            rows[rr][tid] = __ldg(basis + ((size_t)u * NH + fb * 8 + rr) * NK + tid);
        __syncthreads();
        #pragma unroll
        for (int rr = 0; rr < 8; rr++) {
            float bj = rows[rr][tid];
            unsigned long long wp = pk2(bj, bj);
            const ulonglong2* ip = (const ulonglong2*)&rows[rr][ic * 32];
            #pragma unroll
            for (int q = 0; q < 8; q++) {
                ulonglong2 v = ip[q];
                acc[2 * q + 0] = f2fma(v.x, wp, acc[2 * q + 0]);
                acc[2 * q + 1] = f2fma(v.y, wp, acc[2 * q + 1]);
            }
        }
    }
    #pragma unroll
    for (int p = 0; p < 16; p++) {
        float lo, hi;
        upk2(acc[p], lo, hi);
        g_gram[((size_t)u * NK + ic * 32 + 2 * p + 0) * NK + tid] = lo;
        g_gram[((size_t)u * NK + ic * 32 + 2 * p + 1) * NK + tid] = hi;
    }
}

// ---------------- FMA core (4-col, big GEMM) ----------------
__device__ __forceinline__ void fma_row(const float* xsk, float4 w,
                                        unsigned long long* acc) {
    unsigned long long wx = pk2(w.x, w.x);
    unsigned long long wy = pk2(w.y, w.y);
    unsigned long long wz = pk2(w.z, w.z);
    unsigned long long ww = pk2(w.w, w.w);
    const ulonglong2* xr = (const ulonglong2*)xsk;
    ulonglong2 q0 = xr[0], q1 = xr[1], q2 = xr[2], q3 = xr[3];
    unsigned long long xp[8] = {q0.x, q0.y, q1.x, q1.y, q2.x, q2.y, q3.x, q3.y};
    #pragma unroll
    for (int p = 0; p < 8; p++) {
        acc[0 * 8 + p] = f2fma(xp[p], wx, acc[0 * 8 + p]);
        acc[1 * 8 + p] = f2fma(xp[p], wy, acc[1 * 8 + p]);
        acc[2 * 8 + p] = f2fma(xp[p], wz, acc[2 * 8 + p]);
        acc[3 * 8 + p] = f2fma(xp[p], ww, acc[3 * 8 + p]);
    }
}

// ---------------- FMA core (2-col, hash GEMM) ----------------
__device__ __forceinline__ void fma_row2(const float* xsk, float2 w,
                                         unsigned long long* acc) {
    unsigned long long wx = pk2(w.x, w.x);
    unsigned long long wy = pk2(w.y, w.y);
    const ulonglong2* xr = (const ulonglong2*)xsk;
    ulonglong2 q0 = xr[0], q1 = xr[1], q2 = xr[2], q3 = xr[3];
    unsigned long long xp[8] = {q0.x, q0.y, q1.x, q1.y, q2.x, q2.y, q3.x, q3.y};
    #pragma unroll
    for (int p = 0; p < 8; p++) {
        acc[0 * 8 + p] = f2fma(xp[p], wx, acc[0 * 8 + p]);
        acc[1 * 8 + p] = f2fma(xp[p], wy, acc[1 * 8 + p]);
    }
}

// ---------------- big GEMM partial (4 cols, PF=4) — PROVEN config, do not touch ------
template <bool STREAM, int TPB, int KLEN, int MAXB>
__global__ void __launch_bounds__(TPB, MAXB)
k_gemm4(const float* __restrict__ X, const float* __restrict__ W,
        int N, float* __restrict__ out) {
    __shared__ float xs[KLEN][16];
    int tid = threadIdx.x;
    int col = (blockIdx.x * TPB + tid) * 4;
    int k0 = blockIdx.y * KLEN;

    #pragma unroll 4
    for (int idx = tid; idx < KLEN * 4; idx += TPB) {   // float4 units
        int b = idx & 15;
        int kq = idx >> 4;
        float4 v = *(const float4*)(X + (size_t)b * ND + k0 + kq * 4);
        xs[kq * 4 + 0][b] = v.x;
        xs[kq * 4 + 1][b] = v.y;
        xs[kq * 4 + 2][b] = v.z;
        xs[kq * 4 + 3][b] = v.w;
    }

    unsigned long long acc[32];
    #pragma unroll
    for (int i = 0; i < 32; i++) acc[i] = 0ull;

    const float* Wp = W + (size_t)k0 * N + col;
    const float* Wpf = Wp + (size_t)4 * N;
    float4 wbuf[4];
    #pragma unroll
    for (int i = 0; i < 4; i++)
        wbuf[i] = STREAM ? __ldcs((const float4*)(Wp + (size_t)i * N))
                         : __ldg((const float4*)(Wp + (size_t)i * N));

    __syncthreads();

    #pragma unroll 4
    for (int k = 0; k < KLEN - 4; k++) {
        float4 w = wbuf[k & 3];
        wbuf[k & 3] = STREAM ? __ldcs((const float4*)Wpf)
                             : __ldg((const float4*)Wpf);
        Wpf += N;
        fma_row(&xs[k][0], w, acc);
    }
    #pragma unroll
    for (int k = KLEN - 4; k < KLEN; k++)
        fma_row(&xs[k][0], wbuf[k & 3], acc);

    float* op = out + (size_t)blockIdx.y * (NB * (size_t)N) + col;
    #pragma unroll
    for (int p = 0; p < 8; p++) {
        float4 r0, r1;
        upk2(acc[0 * 8 + p], r0.x, r1.x);
        upk2(acc[1 * 8 + p], r0.y, r1.y);
        upk2(acc[2 * 8 + p], r0.z, r1.z);
        upk2(acc[3 * 8 + p], r0.w, r1.w);
        *(float4*)(op + (size_t)(2 * p + 0) * N) = r0;
        *(float4*)(op + (size_t)(2 * p + 1) * N) = r1;
    }
}

// ---------------- hash GEMM partial: 2 cols/thread, PF=8, grid (4, KS_HASH) ----------
__global__ void __launch_bounds__(128, 4)
k_hgemm2(const float* __restrict__ X, const float* __restrict__ P,
         float* __restrict__ out) {
    __shared__ float xs[KL_HASH][16];
    const int N = NH;
    int tid = threadIdx.x;
    int col = (blockIdx.x * 128 + tid) * 2;
    int k0 = blockIdx.y * KL_HASH;

    // stage X[:, k0..k0+64) transposed into xs[k][b]
    #pragma unroll
    for (int idx = tid; idx < KL_HASH * 4; idx += 128) {   // float4 units
        int b = idx & 15;
        int kq = idx >> 4;
        float4 v = *(const float4*)(X + (size_t)b * ND + k0 + kq * 4);
        xs[kq * 4 + 0][b] = v.x;
        xs[kq * 4 + 1][b] = v.y;
        xs[kq * 4 + 2][b] = v.z;
        xs[kq * 4 + 3][b] = v.w;
    }

    unsigned long long acc[16];
    #pragma unroll
    for (int i = 0; i < 16; i++) acc[i] = 0ull;

    const float* Pp = P + (size_t)k0 * N + col;
    const float* Ppf = Pp + (size_t)8 * N;
    float2 wbuf[8];
    #pragma unroll
    for (int i = 0; i < 8; i++)
        wbuf[i] = __ldg((const float2*)(Pp + (size_t)i * N));

    __syncthreads();

    #pragma unroll 8
    for (int k = 0; k < KL_HASH - 8; k++) {
        float2 w = wbuf[k & 7];
        wbuf[k & 7] = __ldg((const float2*)Ppf);
        Ppf += N;
        fma_row2(&xs[k][0], w, acc);
    }
    #pragma unroll
    for (int k = KL_HASH - 8; k < KL_HASH; k++)
        fma_row2(&xs[k][0], wbuf[k & 7], acc);

    float* op = out + (size_t)blockIdx.y * (NB * (size_t)N) + col;
    #pragma unroll
    for (int p = 0; p < 8; p++) {
        float2 r0, r1;
        upk2(acc[0 * 8 + p], r0.x, r1.x);
        upk2(acc[1 * 8 + p], r0.y, r1.y);
        *(float2*)(op + (size_t)(2 * p + 0) * N) = r0;
        *(float2*)(op + (size_t)(2 * p + 1) * N) = r1;
    }
}

// ---------------- reduce KS_BIG partials + bias[route from amax] + tanh -> xf_next ---
__global__ void k_reduce_tanh(const float* __restrict__ bias, float* __restrict__ Xout) {
    int idx = blockIdx.x * 256 + threadIdx.x;      // float4 index, 49152 total
    int b = idx / 3072;
    int j = (idx - b * 3072) * 4;
    size_t o = (size_t)b * ND + j;
    float4 s = make_float4(0.f, 0.f, 0.f, 0.f);
    #pragma unroll
    for (int t = 0; t < KS_BIG; t++) {
        float4 v = *(const float4*)(g_part + (size_t)t * (NB * ND) + o);
        s.x += v.x; s.y += v.y; s.z += v.z; s.w += v.w;
    }
    int r = 31 - (int)(g_amax[b] & 0xffull);       // decode route directly
    float4 bv = *(const float4*)(bias + (size_t)r * ND + j);
    float4 res;
    res.x = tanhf(s.x + bv.x);
    res.y = tanhf(s.y + bv.y);
    res.z = tanhf(s.z + bv.z);
    res.w = tanhf(s.w + bv.w);
    *(float4*)(Xout + o) = res;
}

// ---------------- reduce KS_HASH hash partials -> g_h; also reset g_amax ------------
__global__ void __launch_bounds__(256) k_hreduce() {
    int tid = threadIdx.x;
    if (blockIdx.x == 0 && tid < NB) g_amax[tid] = 0ull;
    int o = tid & 31;                      // output within block (float4)
    int g = tid >> 5;                      // p-group 0..7
    int e4 = blockIdx.x * 32 + o;          // float4 elem 0..4095
    __shared__ float4 red[256];

    float4 s = make_float4(0.f, 0.f, 0.f, 0.f);
    #pragma unroll 8
    for (int p = 0; p < KS_HASH / 8; p++) {
        float4 v = *(const float4*)(g_hpart +
                                    (size_t)(g * (KS_HASH / 8) + p) * (NB * NH) + e4 * 4);
        s.x += v.x; s.y += v.y; s.z += v.z; s.w += v.w;
    }
    red[g * 32 + o] = s;
    __syncthreads();
    #pragma unroll
    for (int gg = 4; gg >= 1; gg >>= 1) {
        if (g < gg) {
            float4 a = red[g * 32 + o];
            float4 c = red[(g + gg) * 32 + o];
            a.x += c.x; a.y += c.y; a.z += c.z; a.w += c.w;
            red[g * 32 + o] = a;
        }
        __syncthreads();
    }
    if (g == 0) *(float4*)(g_h + e4 * 4) = red[o];
}

// ---------------- coeff partial: coeffp[fc][u][b][k] = sum_{f chunk} h[b][f]*basis[u][f][k] ----
// grid (32, FC): u, f-chunk of 128. 128 threads = k.
__global__ void __launch_bounds__(128) k_coeff(const float* __restrict__ basis) {
    int u = blockIdx.x;
    int fc = blockIdx.y;
    int tid = threadIdx.x;
    __shared__ float hs[128][16];
    #pragma unroll
    for (int it = 0; it < 16; it++) {
        int idx = tid + it * 128;
        int b = idx & 15;
        int f = idx >> 4;
        hs[f][b] = g_h[b * NH + fc * 128 + f];
    }
    __syncthreads();

    unsigned long long acc[8];
    #pragma unroll
    for (int i = 0; i < 8; i++) acc[i] = 0ull;

    const float* bp = basis + ((size_t)u * NH + fc * 128) * NK + tid;
    #pragma unroll 16
    for (int f = 0; f < 128; f++) {
        float bv = __ldg(bp + (size_t)f * NK);
        unsigned long long wp = pk2(bv, bv);
        const ulonglong2* xr = (const ulonglong2*)&hs[f][0];
        ulonglong2 q0 = xr[0], q1 = xr[1], q2 = xr[2], q3 = xr[3];
        acc[0] = f2fma(q0.x, wp, acc[0]);
        acc[1] = f2fma(q0.y, wp, acc[1]);
        acc[2] = f2fma(q1.x, wp, acc[2]);
        acc[3] = f2fma(q1.y, wp, acc[3]);
        acc[4] = f2fma(q2.x, wp, acc[4]);
        acc[5] = f2fma(q2.y, wp, acc[5]);
        acc[6] = f2fma(q3.x, wp, acc[6]);
        acc[7] = f2fma(q3.y, wp, acc[7]);
    }
    #pragma unroll
    for (int p = 0; p < 8; p++) {
        float lo, hi;
        upk2(acc[p], lo, hi);
        g_coeffp[(((size_t)fc * NU + u) * NB + 2 * p + 0) * NK + tid] = lo;
        g_coeffp[(((size_t)fc * NU + u) * NB + 2 * p + 1) * NK + tid] = hi;
    }
}

// ---------------- mags + fused masked argmax: c^T G c -> encoded atomicMax ----------
__global__ void __launch_bounds__(128) k_mags(int step) {
    int b = blockIdx.x;
    int u = blockIdx.y;
    int tid = threadIdx.x;
    __shared__ float cs[128];
    __shared__ float red[128];

    float c = 0.f;
    #pragma unroll
    for (int fc = 0; fc < FC; fc++)
        c += g_coeffp[(((size_t)fc * NU + u) * NB + b) * NK + tid];
    cs[tid] = c;
    g_coeff[((size_t)b * NU + u) * NK + tid] = c;
    __syncthreads();

    float v = 0.f;
    const float* gp = g_gram + (size_t)u * NK * NK + tid;
    #pragma unroll 8
    for (int i = 0; i < 128; i++) v += gp[(size_t)i * NK] * cs[i];
    red[tid] = v * cs[tid];
    __syncthreads();
    for (int off = 64; off > 0; off >>= 1) {
        if (tid < off) red[tid] += red[tid + off];
        __syncthreads();
    }
    if (tid == 0) {
        float m = fmaxf(red[0], 0.0f);
        bool masked = false;
        for (int t = 0; t < step; t++)
            if (g_routeh[b * NDEPTH + t] == u) masked = true;
        if (!masked) {
            unsigned long long e =
                ((unsigned long long)__float_as_uint(m) << 32) |
                (unsigned long long)(31 - u);
            atomicMax(&g_amax[b], e);
        }
    }
}

// ---------------- residual: decode route; out[b][f] += h[b][f] - (basis[u] @ c)[f] ----
__global__ void __launch_bounds__(128) k_resid(const float* __restrict__ basis,
                                               float* __restrict__ out,
                                               int step, float* __restrict__ routes_out) {
    int b = blockIdx.x;
    int fc = blockIdx.y;
    int tid = threadIdx.x;
    int f = fc * 128 + tid;
    __shared__ float cs[128];
    __shared__ int su;
    if (tid == 0) {
        int u = 31 - (int)(g_amax[b] & 0xffull);
        su = u;
        if (fc == 0) {
            g_routeh[b * NDEPTH + step] = u;
            if (routes_out) routes_out[b * NDEPTH + step] = (float)u;
        }
    }
    __syncthreads();
    int u = su;
    cs[tid] = g_coeff[((size_t)b * NU + u) * NK + tid];
    __syncthreads();

    float acc = 0.f;
    const float4* bp = (const float4*)(basis + ((size_t)u * NH + f) * NK);
    #pragma unroll 8
    for (int kq = 0; kq < 32; kq++) {
        float4 v = __ldg(bp + kq);
        acc += v.x * cs[kq * 4 + 0] + v.y * cs[kq * 4 + 1] +
               v.z * cs[kq * 4 + 2] + v.w * cs[kq * 4 + 3];
    }
    int o = b * NH + f;
    out[o] += g_h[o] - acc;
}

// ---------------- launch: two-stream fork/join (R10 topology, evR after mags) --------
extern "C" void kernel_launch(void* const* d_in, const int* in_sizes, int n_in,
                              void* d_out, int out_size) {
    (void)in_sizes; (void)n_in;
    const float* x     = (const float*)d_in[0];
    const float* P     = (const float*)d_in[1];
    const float* basis = (const float*)d_in[2];
    const float* Wt    = (const float*)d_in[3];
    const float* bias  = (const float*)d_in[4];
    float* out = (float*)d_out;
    float* routes_out = (out_size >= NB * NH + NB * NDEPTH) ? out + NB * NH : nullptr;

    float *p_xf = nullptr, *p_part = nullptr, *p_hpart = nullptr;
    cudaGetSymbolAddress((void**)&p_xf, g_xf);
    cudaGetSymbolAddress((void**)&p_part, g_part);
    cudaGetSymbolAddress((void**)&p_hpart, g_hpart);

    // one-time resource setup (no device memory allocation; identical work every call)
    static cudaStream_t s2 = nullptr;
    static cudaEvent_t ev0 = nullptr, evR = nullptr, evX = nullptr, evF = nullptr;
    if (s2 == nullptr) {
        int lo = 0, hi = 0;
        cudaDeviceGetStreamPriorityRange(&lo, &hi);
        cudaStreamCreateWithPriority(&s2, cudaStreamNonBlocking, hi);
        cudaEventCreateWithFlags(&ev0, cudaEventDisableTiming);
        cudaEventCreateWithFlags(&evR, cudaEventDisableTiming);
        cudaEventCreateWithFlags(&evX, cudaEventDisableTiming);
        cudaEventCreateWithFlags(&evF, cudaEventDisableTiming);
    }

    // fork: s2 joins the capture via ev0 recorded on the origin stream
    cudaEventRecord(ev0, 0);
    cudaStreamWaitEvent(s2, ev0, 0);

    // ---- s2 prologue: init out, gram, initial hash + routing step 0 ----
    k_init<<<64, 256, 0, s2>>>(out);
    k_gram<<<dim3(32, 4), 128, 0, s2>>>(basis);
    k_hgemm2<<<dim3(4, KS_HASH), 128, 0, s2>>>(x, P, p_hpart);
    k_hreduce<<<128, 256, 0, s2>>>();
    k_coeff<<<dim3(32, FC), 128, 0, s2>>>(basis);
    k_mags<<<dim3(16, 32), 128, 0, s2>>>(0);
    cudaEventRecord(evR, s2);
    k_resid<<<dim3(16, 8), 128, 0, s2>>>(basis, out, 0, routes_out);

    // ---- main prologue: s=0 big GEMM (only needs x) ----
    k_gemm4<true, 256, KL_BIG, 2><<<dim3(12, KS_BIG), 256>>>(x, Wt, ND, p_part);
    cudaStreamWaitEvent(0, evR, 0);
    k_reduce_tanh<<<192, 256>>>(bias, p_xf);              // Xn0 = g_xf[0]
    cudaEventRecord(evX, 0);

    for (int s = 1; s < NDEPTH; s++) {
        const float* Xc = p_xf + (size_t)((s - 1) & 1) * NB * ND;  // Xn_{s-1}

        // s2: hash of Xn_{s-1} + routing step s
        cudaStreamWaitEvent(s2, evX, 0);
        k_hgemm2<<<dim3(4, KS_HASH), 128, 0, s2>>>(Xc, P, p_hpart);
        k_hreduce<<<128, 256, 0, s2>>>();
        k_coeff<<<dim3(32, FC), 128, 0, s2>>>(basis);
        k_mags<<<dim3(16, 32), 128, 0, s2>>>(s);
        cudaEventRecord(evR, s2);
        k_resid<<<dim3(16, 8), 128, 0, s2>>>(basis, out, s, routes_out);

        if (s < NDEPTH - 1) {
            // main: big GEMM for this step (reads Xn_{s-1}, main-stream ordered)
            k_gemm4<true, 256, KL_BIG, 2><<<dim3(12, KS_BIG), 256>>>(Xc, Wt, ND, p_part);
            cudaStreamWaitEvent(0, evR, 0);
            float* Xn = p_xf + (size_t)(s & 1) * NB * ND;
            k_reduce_tanh<<<192, 256>>>(bias, Xn);
            cudaEventRecord(evX, 0);
        }
    }
    // final join: all s2 work (incl. last resid writing `out`) back into origin stream
    cudaEventRecord(evF, s2);
    cudaStreamWaitEvent(0, evF, 0);
}

// round 16
// speedup vs baseline: 1.2136x; 1.0099x over previous
#include <cuda_runtime.h>
#include <cuda_bf16.h>
#include <math.h>
#include <stdint.h>

// Problem constants (fixed by setup_inputs)
#define ND 12288   // D
#define NH 1024    // HASH
#define NU 32      // units
#define NK 128     // BASIS
#define NB 16      // batch
#define NDEPTH 16

#define KS_BIG 24    // split-K for the D x D transform GEMM (grid 12x24=288)
#define KL_BIG 512   // k-rows per big block
#define KS_HASH 192  // split-K for the hash GEMM (grid 4x192=768 with 2 cols/thread)
#define KL_HASH 64   // k-rows per hash block
#define FC 16        // f-chunks for coeff (64 rows each)

// ---------------- device scratch (no allocations allowed) ----------------
__device__ float g_xf[2 * NB * ND];                 // ping-pong xf
__device__ float g_part[KS_BIG * NB * ND];          // big-GEMM split-K partials
__device__ float g_hpart[KS_HASH * NB * NH];        // hash split-K partials
__device__ float g_h[NB * NH];                      // current hash
__device__ float g_gram[NU * NK * NK];              // per-unit Gram B^T B
__device__ float g_coeffp[FC * NU * NB * NK];       // coeff partials [fc][u][b][k]
__device__ float g_coeff[NB * NU * NK];             // summed coeff [b][u][k]
__device__ unsigned long long g_amax[NB];           // encoded masked argmax
__device__ int   g_routeh[NB * NDEPTH];             // route history (masking)

// ---------------- f32x2 helpers ----------------
__device__ __forceinline__ unsigned long long pk2(float lo, float hi) {
    unsigned long long r;
    asm("mov.b64 %0, {%1, %2};" : "=l"(r) : "f"(lo), "f"(hi));
    return r;
}
__device__ __forceinline__ void upk2(unsigned long long v, float& lo, float& hi) {
    asm("mov.b64 {%0, %1}, %2;" : "=f"(lo), "=f"(hi) : "l"(v));
}
__device__ __forceinline__ unsigned long long f2fma(unsigned long long a,
                                                    unsigned long long b,
                                                    unsigned long long c) {
    unsigned long long d;
    asm("fma.rn.f32x2 %0, %1, %2, %3;" : "=l"(d) : "l"(a), "l"(b), "l"(c));
    return d;
}

// ---------------- zero the hash-accumulator region of d_out ----------------
__global__ void k_init(float* __restrict__ out) {
    int i = blockIdx.x * 256 + threadIdx.x;
    if (i < NB * NH) out[i] = 0.0f;
}

// ---------------- Gram: G[u] = basis[u]^T basis[u] (128x128 per unit) ----------------
__global__ void __launch_bounds__(128) k_gram(const float* __restrict__ basis) {
    int u = blockIdx.x;
    int ic = blockIdx.y;
    int tid = threadIdx.x;
    __shared__ float rows[8][128];
    unsigned long long acc[16];
    #pragma unroll
    for (int p = 0; p < 16; p++) acc[p] = 0ull;

    for (int fb = 0; fb < 128; fb++) {
        __syncthreads();
        #pragma unroll
        for (int rr = 0; rr < 8; rr++)
            rows[rr][tid] = __ldg(basis + ((size_t)u * NH + fb * 8 + rr) * NK + tid);
        __syncthreads();
        #pragma unroll
        for (int rr = 0; rr < 8; rr++) {
            float bj = rows[rr][tid];
            unsigned long long wp = pk2(bj, bj);
            const ulonglong2* ip = (const ulonglong2*)&rows[rr][ic * 32];
            #pragma unroll
            for (int q = 0; q < 8; q++) {
                ulonglong2 v = ip[q];
                acc[2 * q + 0] = f2fma(v.x, wp, acc[2 * q + 0]);
                acc[2 * q + 1] = f2fma(v.y, wp, acc[2 * q + 1]);
            }
        }
    }
    #pragma unroll
    for (int p = 0; p < 16; p++) {
        float lo, hi;
        upk2(acc[p], lo, hi);
        g_gram[((size_t)u * NK + ic * 32 + 2 * p + 0) * NK + tid] = lo;
        g_gram[((size_t)u * NK + ic * 32 + 2 * p + 1) * NK + tid] = hi;
    }
}

// ---------------- FMA core (4-col, big GEMM) ----------------
__device__ __forceinline__ void fma_row(const float* xsk, float4 w,
                                        unsigned long long* acc) {
    unsigned long long wx = pk2(w.x, w.x);
    unsigned long long wy = pk2(w.y, w.y);
    unsigned long long wz = pk2(w.z, w.z);
    unsigned long long ww = pk2(w.w, w.w);
    const ulonglong2* xr = (const ulonglong2*)xsk;
    ulonglong2 q0 = xr[0], q1 = xr[1], q2 = xr[2], q3 = xr[3];
    unsigned long long xp[8] = {q0.x, q0.y, q1.x, q1.y, q2.x, q2.y, q3.x, q3.y};
    #pragma unroll
    for (int p = 0; p < 8; p++) {
        acc[0 * 8 + p] = f2fma(xp[p], wx, acc[0 * 8 + p]);
        acc[1 * 8 + p] = f2fma(xp[p], wy, acc[1 * 8 + p]);
        acc[2 * 8 + p] = f2fma(xp[p], wz, acc[2 * 8 + p]);
        acc[3 * 8 + p] = f2fma(xp[p], ww, acc[3 * 8 + p]);
    }
}

// ---------------- FMA core (2-col, hash GEMM) ----------------
__device__ __forceinline__ void fma_row2(const float* xsk, float2 w,
                                         unsigned long long* acc) {
    unsigned long long wx = pk2(w.x, w.x);
    unsigned long long wy = pk2(w.y, w.y);
    const ulonglong2* xr = (const ulonglong2*)xsk;
    ulonglong2 q0 = xr[0], q1 = xr[1], q2 = xr[2], q3 = xr[3];
    unsigned long long xp[8] = {q0.x, q0.y, q1.x, q1.y, q2.x, q2.y, q3.x, q3.y};
    #pragma unroll
    for (int p = 0; p < 8; p++) {
        acc[0 * 8 + p] = f2fma(xp[p], wx, acc[0 * 8 + p]);
        acc[1 * 8 + p] = f2fma(xp[p], wy, acc[1 * 8 + p]);
    }
}

// ---------------- big GEMM partial (4 cols, PF=4) — PROVEN config, do not touch ------
template <bool STREAM, int TPB, int KLEN, int MAXB>
__global__ void __launch_bounds__(TPB, MAXB)
k_gemm4(const float* __restrict__ X, const float* __restrict__ W,
        int N, float* __restrict__ out) {
    __shared__ float xs[KLEN][16];
    int tid = threadIdx.x;
    int col = (blockIdx.x * TPB + tid) * 4;
    int k0 = blockIdx.y * KLEN;

    #pragma unroll 4
    for (int idx = tid; idx < KLEN * 4; idx += TPB) {   // float4 units
        int b = idx & 15;
        int kq = idx >> 4;
        float4 v = *(const float4*)(X + (size_t)b * ND + k0 + kq * 4);
        xs[kq * 4 + 0][b] = v.x;
        xs[kq * 4 + 1][b] = v.y;
        xs[kq * 4 + 2][b] = v.z;
        xs[kq * 4 + 3][b] = v.w;
    }

    unsigned long long acc[32];
    #pragma unroll
    for (int i = 0; i < 32; i++) acc[i] = 0ull;

    const float* Wp = W + (size_t)k0 * N + col;
    const float* Wpf = Wp + (size_t)4 * N;
    float4 wbuf[4];
    #pragma unroll
    for (int i = 0; i < 4; i++)
        wbuf[i] = STREAM ? __ldcs((const float4*)(Wp + (size_t)i * N))
                         : __ldg((const float4*)(Wp + (size_t)i * N));

    __syncthreads();

    #pragma unroll 4
    for (int k = 0; k < KLEN - 4; k++) {
        float4 w = wbuf[k & 3];
        wbuf[k & 3] = STREAM ? __ldcs((const float4*)Wpf)
                             : __ldg((const float4*)Wpf);
        Wpf += N;
        fma_row(&xs[k][0], w, acc);
    }
    #pragma unroll
    for (int k = KLEN - 4; k < KLEN; k++)
        fma_row(&xs[k][0], wbuf[k & 3], acc);

    float* op = out + (size_t)blockIdx.y * (NB * (size_t)N) + col;
    #pragma unroll
    for (int p = 0; p < 8; p++) {
        float4 r0, r1;
        upk2(acc[0 * 8 + p], r0.x, r1.x);
        upk2(acc[1 * 8 + p], r0.y, r1.y);
        upk2(acc[2 * 8 + p], r0.z, r1.z);
        upk2(acc[3 * 8 + p], r0.w, r1.w);
        *(float4*)(op + (size_t)(2 * p + 0) * N) = r0;
        *(float4*)(op + (size_t)(2 * p + 1) * N) = r1;
    }
}

// ---------------- hash GEMM partial: 2 cols/thread, PF=8, grid (4, KS_HASH) ----------
__global__ void __launch_bounds__(128, 4)
k_hgemm2(const float* __restrict__ X, const float* __restrict__ P,
         float* __restrict__ out) {
    __shared__ float xs[KL_HASH][16];
    const int N = NH;
    int tid = threadIdx.x;
    int col = (blockIdx.x * 128 + tid) * 2;
    int k0 = blockIdx.y * KL_HASH;

    #pragma unroll
    for (int idx = tid; idx < KL_HASH * 4; idx += 128) {   // float4 units
        int b = idx & 15;
        int kq = idx >> 4;
        float4 v = *(const float4*)(X + (size_t)b * ND + k0 + kq * 4);
        xs[kq * 4 + 0][b] = v.x;
        xs[kq * 4 + 1][b] = v.y;
        xs[kq * 4 + 2][b] = v.z;
        xs[kq * 4 + 3][b] = v.w;
    }

    unsigned long long acc[16];
    #pragma unroll
    for (int i = 0; i < 16; i++) acc[i] = 0ull;

    const float* Pp = P + (size_t)k0 * N + col;
    const float* Ppf = Pp + (size_t)8 * N;
    float2 wbuf[8];
    #pragma unroll
    for (int i = 0; i < 8; i++)
        wbuf[i] = __ldg((const float2*)(Pp + (size_t)i * N));

    __syncthreads();

    #pragma unroll 8
    for (int k = 0; k < KL_HASH - 8; k++) {
        float2 w = wbuf[k & 7];
        wbuf[k & 7] = __ldg((const float2*)Ppf);
        Ppf += N;
        fma_row2(&xs[k][0], w, acc);
    }
    #pragma unroll
    for (int k = KL_HASH - 8; k < KL_HASH; k++)
        fma_row2(&xs[k][0], wbuf[k & 7], acc);

    float* op = out + (size_t)blockIdx.y * (NB * (size_t)N) + col;
    #pragma unroll
    for (int p = 0; p < 8; p++) {
        float2 r0, r1;
        upk2(acc[0 * 8 + p], r0.x, r1.x);
        upk2(acc[1 * 8 + p], r0.y, r1.y);
        *(float2*)(op + (size_t)(2 * p + 0) * N) = r0;
        *(float2*)(op + (size_t)(2 * p + 1) * N) = r1;
    }
}

// ---------------- reduce KS_BIG partials + bias[route from amax] + tanh -> xf_next ---
__global__ void k_reduce_tanh(const float* __restrict__ bias, float* __restrict__ Xout) {
    int idx = blockIdx.x * 256 + threadIdx.x;      // float4 index, 49152 total
    int b = idx / 3072;
    int j = (idx - b * 3072) * 4;
    size_t o = (size_t)b * ND + j;
    float4 s = make_float4(0.f, 0.f, 0.f, 0.f);
    #pragma unroll
    for (int t = 0; t < KS_BIG; t++) {
        float4 v = *(const float4*)(g_part + (size_t)t * (NB * ND) + o);
        s.x += v.x; s.y += v.y; s.z += v.z; s.w += v.w;
    }
    int r = 31 - (int)(g_amax[b] & 0xffull);       // decode route directly
    float4 bv = *(const float4*)(bias + (size_t)r * ND + j);
    float4 res;
    res.x = tanhf(s.x + bv.x);
    res.y = tanhf(s.y + bv.y);
    res.z = tanhf(s.z + bv.z);
    res.w = tanhf(s.w + bv.w);
    *(float4*)(Xout + o) = res;
}

// ---------------- reduce KS_HASH hash partials -> g_h; also reset g_amax ------------
// grid 256, 256 threads: 16 float4 outputs x 16 p-groups (12 partials each).
__global__ void __launch_bounds__(256) k_hreduce() {
    int tid = threadIdx.x;
    if (blockIdx.x == 0 && tid < NB) g_amax[tid] = 0ull;
    int o = tid & 15;                      // output within block (float4)
    int g = tid >> 4;                      // p-group 0..15
    int e4 = blockIdx.x * 16 + o;          // float4 elem 0..4095
    __shared__ float4 red[256];

    float4 s = make_float4(0.f, 0.f, 0.f, 0.f);
    #pragma unroll
    for (int p = 0; p < KS_HASH / 16; p++) {
        float4 v = *(const float4*)(g_hpart +
                                    (size_t)(g * (KS_HASH / 16) + p) * (NB * NH) + e4 * 4);
        s.x += v.x; s.y += v.y; s.z += v.z; s.w += v.w;
    }
    red[g * 16 + o] = s;
    __syncthreads();
    #pragma unroll
    for (int gg = 8; gg >= 1; gg >>= 1) {
        if (g < gg) {
            float4 a = red[g * 16 + o];
            float4 c = red[(g + gg) * 16 + o];
            a.x += c.x; a.y += c.y; a.z += c.z; a.w += c.w;
            red[g * 16 + o] = a;
        }
        __syncthreads();
    }
    if (g == 0) *(float4*)(g_h + e4 * 4) = red[o];
}

// ---------------- coeff partial: coeffp[fc][u][b][k] = sum_{f chunk} h[b][f]*basis[u][f][k] ----
// grid (32, FC=16): u, f-chunk of 64. 128 threads = k.
__global__ void __launch_bounds__(128) k_coeff(const float* __restrict__ basis) {
    int u = blockIdx.x;
    int fc = blockIdx.y;
    int tid = threadIdx.x;
    __shared__ float hs[64][16];
    #pragma unroll
    for (int it = 0; it < 8; it++) {
        int idx = tid + it * 128;
        int b = idx & 15;
        int f = idx >> 4;
        hs[f][b] = g_h[b * NH + fc * 64 + f];
    }
    __syncthreads();

    unsigned long long acc[8];
    #pragma unroll
    for (int i = 0; i < 8; i++) acc[i] = 0ull;

    const float* bp = basis + ((size_t)u * NH + fc * 64) * NK + tid;
    #pragma unroll 16
    for (int f = 0; f < 64; f++) {
        float bv = __ldg(bp + (size_t)f * NK);
        unsigned long long wp = pk2(bv, bv);
        const ulonglong2* xr = (const ulonglong2*)&hs[f][0];
        ulonglong2 q0 = xr[0], q1 = xr[1], q2 = xr[2], q3 = xr[3];
        acc[0] = f2fma(q0.x, wp, acc[0]);
        acc[1] = f2fma(q0.y, wp, acc[1]);
        acc[2] = f2fma(q1.x, wp, acc[2]);
        acc[3] = f2fma(q1.y, wp, acc[3]);
        acc[4] = f2fma(q2.x, wp, acc[4]);
        acc[5] = f2fma(q2.y, wp, acc[5]);
        acc[6] = f2fma(q3.x, wp, acc[6]);
        acc[7] = f2fma(q3.y, wp, acc[7]);
    }
    #pragma unroll
    for (int p = 0; p < 8; p++) {
        float lo, hi;
        upk2(acc[p], lo, hi);
        g_coeffp[(((size_t)fc * NU + u) * NB + 2 * p + 0) * NK + tid] = lo;
        g_coeffp[(((size_t)fc * NU + u) * NB + 2 * p + 1) * NK + tid] = hi;
    }
}

// ---------------- mags + fused masked argmax: 4 exemplars per block share one Gram pass
// grid (4, 32): b-quad, u. 128 threads = j.
__global__ void __launch_bounds__(128) k_mags(int step) {
    int bq = blockIdx.x;           // b = bq*4 .. bq*4+3
    int u = blockIdx.y;
    int tid = threadIdx.x;
    __shared__ float cs[4][128];
    __shared__ float red[4][128];

    #pragma unroll
    for (int bb = 0; bb < 4; bb++) {
        int b = bq * 4 + bb;
        float c = 0.f;
        #pragma unroll
        for (int fc = 0; fc < FC; fc++)
            c += g_coeffp[(((size_t)fc * NU + u) * NB + b) * NK + tid];
        cs[bb][tid] = c;
        g_coeff[((size_t)b * NU + u) * NK + tid] = c;
    }
    __syncthreads();

    float v0 = 0.f, v1 = 0.f, v2 = 0.f, v3 = 0.f;
    const float* gp = g_gram + (size_t)u * NK * NK + tid;
    #pragma unroll 8
    for (int i = 0; i < 128; i++) {
        float g = gp[(size_t)i * NK];
        v0 += g * cs[0][i];
        v1 += g * cs[1][i];
        v2 += g * cs[2][i];
        v3 += g * cs[3][i];
    }
    red[0][tid] = v0 * cs[0][tid];
    red[1][tid] = v1 * cs[1][tid];
    red[2][tid] = v2 * cs[2][tid];
    red[3][tid] = v3 * cs[3][tid];
    __syncthreads();
    for (int off = 64; off > 0; off >>= 1) {
        if (tid < off) {
            #pragma unroll
            for (int bb = 0; bb < 4; bb++)
                red[bb][tid] += red[bb][tid + off];
        }
        __syncthreads();
    }
    if (tid < 4) {
        int b = bq * 4 + tid;
        float m = fmaxf(red[tid][0], 0.0f);
        bool masked = false;
        for (int t = 0; t < step; t++)
            if (g_routeh[b * NDEPTH + t] == u) masked = true;
        if (!masked) {
            unsigned long long e =
                ((unsigned long long)__float_as_uint(m) << 32) |
                (unsigned long long)(31 - u);
            atomicMax(&g_amax[b], e);
        }
    }
}

// ---------------- residual: decode route; out[b][f] += h[b][f] - (basis[u] @ c)[f] ----
__global__ void __launch_bounds__(128) k_resid(const float* __restrict__ basis,
                                               float* __restrict__ out,
                                               int step, float* __restrict__ routes_out) {
    int b = blockIdx.x;
    int fc = blockIdx.y;
    int tid = threadIdx.x;
    int f = fc * 128 + tid;
    __shared__ float cs[128];
    __shared__ int su;
    if (tid == 0) {
        int u = 31 - (int)(g_amax[b] & 0xffull);
        su = u;
        if (fc == 0) {
            g_routeh[b * NDEPTH + step] = u;
            if (routes_out) routes_out[b * NDEPTH + step] = (float)u;
        }
    }
    __syncthreads();
    int u = su;
    cs[tid] = g_coeff[((size_t)b * NU + u) * NK + tid];
    __syncthreads();

    float acc = 0.f;
    const float4* bp = (const float4*)(basis + ((size_t)u * NH + f) * NK);
    #pragma unroll 8
    for (int kq = 0; kq < 32; kq++) {
        float4 v = __ldg(bp + kq);
        acc += v.x * cs[kq * 4 + 0] + v.y * cs[kq * 4 + 1] +
               v.z * cs[kq * 4 + 2] + v.w * cs[kq * 4 + 3];
    }
    int o = b * NH + f;
    out[o] += g_h[o] - acc;
}

// ---------------- launch: two-stream fork/join (R15 topology) -----------------------
extern "C" void kernel_launch(void* const* d_in, const int* in_sizes, int n_in,
                              void* d_out, int out_size) {
    (void)in_sizes; (void)n_in;
    const float* x     = (const float*)d_in[0];
    const float* P     = (const float*)d_in[1];
    const float* basis = (const float*)d_in[2];
    const float* Wt    = (const float*)d_in[3];
    const float* bias  = (const float*)d_in[4];
    float* out = (float*)d_out;
    float* routes_out = (out_size >= NB * NH + NB * NDEPTH) ? out + NB * NH : nullptr;

    float *p_xf = nullptr, *p_part = nullptr, *p_hpart = nullptr;
    cudaGetSymbolAddress((void**)&p_xf, g_xf);
    cudaGetSymbolAddress((void**)&p_part, g_part);
    cudaGetSymbolAddress((void**)&p_hpart, g_hpart);

    // one-time resource setup (no device memory allocation; identical work every call)
    static cudaStream_t s2 = nullptr;
    static cudaEvent_t ev0 = nullptr, evR = nullptr, evX = nullptr, evF = nullptr;
    if (s2 == nullptr) {
        int lo = 0, hi = 0;
        cudaDeviceGetStreamPriorityRange(&lo, &hi);
        cudaStreamCreateWithPriority(&s2, cudaStreamNonBlocking, hi);
        cudaEventCreateWithFlags(&ev0, cudaEventDisableTiming);
        cudaEventCreateWithFlags(&evR, cudaEventDisableTiming);
        cudaEventCreateWithFlags(&evX, cudaEventDisableTiming);
        cudaEventCreateWithFlags(&evF, cudaEventDisableTiming);
    }

    // fork: s2 joins the capture via ev0 recorded on the origin stream
    cudaEventRecord(ev0, 0);
    cudaStreamWaitEvent(s2, ev0, 0);

    // ---- s2 prologue: init out, gram, initial hash + routing step 0 ----
    k_init<<<64, 256, 0, s2>>>(out);
    k_gram<<<dim3(32, 4), 128, 0, s2>>>(basis);
    k_hgemm2<<<dim3(4, KS_HASH), 128, 0, s2>>>(x, P, p_hpart);
    k_hreduce<<<256, 256, 0, s2>>>();
    k_coeff<<<dim3(32, FC), 128, 0, s2>>>(basis);
    k_mags<<<dim3(4, 32), 128, 0, s2>>>(0);
    cudaEventRecord(evR, s2);
    k_resid<<<dim3(16, 8), 128, 0, s2>>>(basis, out, 0, routes_out);

    // ---- main prologue: s=0 big GEMM (only needs x) ----
    k_gemm4<true, 256, KL_BIG, 2><<<dim3(12, KS_BIG), 256>>>(x, Wt, ND, p_part);
    cudaStreamWaitEvent(0, evR, 0);
    k_reduce_tanh<<<192, 256>>>(bias, p_xf);              // Xn0 = g_xf[0]
    cudaEventRecord(evX, 0);

    for (int s = 1; s < NDEPTH; s++) {
        const float* Xc = p_xf + (size_t)((s - 1) & 1) * NB * ND;  // Xn_{s-1}

        // s2: hash of Xn_{s-1} + routing step s
        cudaStreamWaitEvent(s2, evX, 0);
        k_hgemm2<<<dim3(4, KS_HASH), 128, 0, s2>>>(Xc, P, p_hpart);
        k_hreduce<<<256, 256, 0, s2>>>();
        k_coeff<<<dim3(32, FC), 128, 0, s2>>>(basis);
        k_mags<<<dim3(4, 32), 128, 0, s2>>>(s);
        cudaEventRecord(evR, s2);
        k_resid<<<dim3(16, 8), 128, 0, s2>>>(basis, out, s, routes_out);

        if (s < NDEPTH - 1) {
            // main: big GEMM for this step (reads Xn_{s-1}, main-stream ordered)
            k_gemm4<true, 256, KL_BIG, 2><<<dim3(12, KS_BIG), 256>>>(Xc, Wt, ND, p_part);
            cudaStreamWaitEvent(0, evR, 0);
            float* Xn = p_xf + (size_t)(s & 1) * NB * ND;
            k_reduce_tanh<<<192, 256>>>(bias, Xn);
            cudaEventRecord(evX, 0);
        }
    }
    // final join: all s2 work (incl. last resid writing `out`) back into origin stream
    cudaEventRecord(evF, s2);
    cudaStreamWaitEvent(0, evF, 0);
}